// round 3
// baseline (speedup 1.0000x reference)
#include <cuda_runtime.h>

#define BN_EPS 1e-5f

// Scratch (allocation-free rule: __device__ globals)
__device__ float g_y[8 * 64 * 64 * 64];    // (b, o, hy, wy) conv1+bn+relu result at 64x64
__device__ float g_res[8 * 128 * 128];     // (b, h, w) channel-mean of ref

// ---------------- f32x2 packed-FMA helpers (Blackwell dual-rate fp32) -------
typedef unsigned long long u64;

__device__ __forceinline__ u64 pack2(float lo, float hi) {
    u64 r;
    asm("mov.b64 %0, {%1, %2};" : "=l"(r) : "f"(lo), "f"(hi));
    return r;
}
__device__ __forceinline__ void unpack2(u64 v, float& lo, float& hi) {
    asm("mov.b64 {%0, %1}, %2;" : "=f"(lo), "=f"(hi) : "l"(v));
}
__device__ __forceinline__ void fma2(u64& d, u64 a, u64 b) {
    asm("fma.rn.f32x2 %0, %1, %2, %0;" : "+l"(d) : "l"(a), "l"(b));
}

// ---------------- Kernel 1: res = mean over channels of ref -----------------
__global__ void __launch_bounds__(256) res_kernel(const float* __restrict__ ref) {
    int idx = blockIdx.x * 256 + threadIdx.x;     // 131072 total pixels
    int b = idx >> 14;                            // / 16384
    int p = idx & 16383;
    const float* src = ref + (size_t)b * 64 * 16384 + p;
    float s = 0.f;
#pragma unroll
    for (int c = 0; c < 64; c++) s += src[(size_t)c * 16384];
    g_res[idx] = s * (1.0f / 64.0f);
}

// ---------------- Kernel 2: y = relu(bn1(conv1(x))) at 64x64 ----------------
__global__ void __launch_bounds__(256) conv1_kernel(
    const float* __restrict__ x,  const float* __restrict__ w1,
    const float* __restrict__ b1, const float* __restrict__ g1,
    const float* __restrict__ bt1, const float* __restrict__ m1,
    const float* __restrict__ v1)
{
    __shared__ __align__(16) float s_x[64 * 64];    // [c][w]
    __shared__ __align__(16) float s_wt[64 * 64];   // [c][o] transposed
    __shared__ float s_A[64], s_B[64];

    int h = blockIdx.x, b = blockIdx.y;
    int t = threadIdx.x;

    if (t < 64) {
        float sc = g1[t] * rsqrtf(v1[t] + BN_EPS);
        s_A[t] = sc;
        s_B[t] = b1[t] * sc + bt1[t] - m1[t] * sc;
    }
    const float* xrow = x + (size_t)b * 64 * 4096 + (size_t)h * 64;
    for (int i = t; i < 1024; i += 256) {           // float4 loads: 64c x 16 quads
        int c = i >> 4, w4 = (i & 15) * 4;
        *(float4*)&s_x[c * 64 + w4] = *(const float4*)&xrow[(size_t)c * 4096 + w4];
    }
    for (int i = t; i < 4096; i += 256) {           // transposed weights
        int o = i & 63, c = i >> 6;
        s_wt[i] = w1[o * 64 + c];                   // s_wt[c*64+o]
    }
    __syncthreads();

    int wg = t & 31, og = t >> 5;
    int w0 = wg * 2, o0 = og * 8;

    u64 acc[4][2];                                  // [o-pair][w]
#pragma unroll
    for (int i = 0; i < 4; i++)
#pragma unroll
        for (int j = 0; j < 2; j++) acc[i][j] = 0ull;

#pragma unroll 8
    for (int c = 0; c < 64; c++) {
        float2 rv = *(const float2*)&s_x[c * 64 + w0];
        u64 r0 = pack2(rv.x, rv.x);
        u64 r1 = pack2(rv.y, rv.y);
        const u64* wp = (const u64*)&s_wt[c * 64 + o0];
        u64 wv0 = wp[0], wv1 = wp[1], wv2 = wp[2], wv3 = wp[3];
        fma2(acc[0][0], wv0, r0); fma2(acc[0][1], wv0, r1);
        fma2(acc[1][0], wv1, r0); fma2(acc[1][1], wv1, r1);
        fma2(acc[2][0], wv2, r0); fma2(acc[2][1], wv2, r1);
        fma2(acc[3][0], wv3, r0); fma2(acc[3][1], wv3, r1);
    }

    float* ybase = g_y + (size_t)b * 64 * 4096 + (size_t)h * 64;
#pragma unroll
    for (int i = 0; i < 4; i++) {
        int oA = o0 + 2 * i, oB = oA + 1;
        float A0 = s_A[oA], B0 = s_B[oA];
        float A1 = s_A[oB], B1 = s_B[oB];
#pragma unroll
        for (int j = 0; j < 2; j++) {
            float lo, hi;
            unpack2(acc[i][j], lo, hi);
            ybase[(size_t)oA * 4096 + w0 + j] = fmaxf(lo * A0 + B0, 0.f);
            ybase[(size_t)oB * 4096 + w0 + j] = fmaxf(hi * A1 + B1, 0.f);
        }
    }
}

// ---------------- Kernel 3: fused mask + aggregate + conv2 ------------------
// Shared layout (floats):
//   s_ref  [64*128] : ref[b, :, h, :]
//   s_wt   [64*64]  : w2 transposed [c][o]
//   s_y    [2][64*64]: two y rows (r0, r1)
//   s_res  [3*132]  : res rows h-1,h,h+1 zero padded (col = w+1)
//   s_A,s_B [64]    : folded BN2
#define FUSE_SMEM_FLOATS (8192 + 4096 + 8192 + 396 + 64 + 64)
#define FUSE_SMEM_BYTES  (FUSE_SMEM_FLOATS * 4)

__global__ void __launch_bounds__(256, 2) fuse_kernel(
    const float* __restrict__ ref, const float* __restrict__ w2,
    const float* __restrict__ b2,  const float* __restrict__ g2,
    const float* __restrict__ bt2, const float* __restrict__ m2,
    const float* __restrict__ v2,  float* __restrict__ out)
{
    extern __shared__ float sm[];
    float* s_ref = sm;              // 8192
    float* s_wt  = sm + 8192;       // 4096
    float* s_y   = sm + 12288;      // 8192 (buf0 then buf1)
    float* s_res = sm + 20480;      // 396
    float* s_A   = sm + 20876;      // 64
    float* s_B   = sm + 20940;      // 64

    int h = blockIdx.x, b = blockIdx.y;
    int t = threadIdx.x;

    if (t < 64) {
        float sc = g2[t] * rsqrtf(v2[t] + BN_EPS);
        s_A[t] = sc;
        s_B[t] = b2[t] * sc + bt2[t] - m2[t] * sc;
    }

    const float* rrow = ref + (size_t)b * 64 * 16384 + (size_t)h * 128;
    for (int i = t; i < 2048; i += 256) {           // float4: 64c x 32 quads
        int c = i >> 5, w4 = (i & 31) * 4;
        *(float4*)&s_ref[c * 128 + w4] = *(const float4*)&rrow[(size_t)c * 16384 + w4];
    }
    for (int i = t; i < 4096; i += 256) {
        int o = i & 63, c = i >> 6;
        s_wt[i] = w2[o * 64 + c];
    }

    // y rows: the 9 upsampled taps collapse to 2 y rows
    int r0 = (h - 1) >> 1; if (r0 < 0) r0 = 0;
    int r1 = (h + 1) >> 1; if (r1 > 63) r1 = 63;
    const float* ybase = g_y + (size_t)b * 64 * 4096;
    for (int i = t; i < 1024; i += 256) {           // float4: 64o x 16 quads
        int o = i >> 4, w4 = (i & 15) * 4;
        *(float4*)&s_y[o * 64 + w4]        = *(const float4*)&ybase[(size_t)o * 4096 + r0 * 64 + w4];
        *(float4*)&s_y[4096 + o * 64 + w4] = *(const float4*)&ybase[(size_t)o * 4096 + r1 * 64 + w4];
    }

    // res rows, zero padded: s_res[j*132 + (w+1)] = res[h-1+j][w]
    for (int i = t; i < 3 * 132; i += 256) {
        int j = i / 132, col = i % 132;
        int rr = h - 1 + j, wc = col - 1;
        float v = 0.f;
        if (col < 130 && rr >= 0 && rr < 128 && wc >= 0 && wc < 128)
            v = g_res[((size_t)b * 128 + rr) * 128 + wc];
        s_res[i] = v;
    }
    __syncthreads();

    int wg = t & 31, og = t >> 5;
    int w0 = wg * 4, o0 = og * 8;

    // ---- conv2 GEMM: 8 o x 4 w per thread, f32x2 packed along o ----
    u64 acc[4][4];
#pragma unroll
    for (int i = 0; i < 4; i++)
#pragma unroll
        for (int j = 0; j < 4; j++) acc[i][j] = 0ull;

#pragma unroll 8
    for (int c = 0; c < 64; c++) {
        float4 rv = *(const float4*)&s_ref[c * 128 + w0];
        u64 rr0 = pack2(rv.x, rv.x);
        u64 rr1 = pack2(rv.y, rv.y);
        u64 rr2 = pack2(rv.z, rv.z);
        u64 rr3 = pack2(rv.w, rv.w);
        const u64* wp = (const u64*)&s_wt[c * 64 + o0];
        u64 wv0 = wp[0], wv1 = wp[1], wv2 = wp[2], wv3 = wp[3];
        fma2(acc[0][0], wv0, rr0); fma2(acc[0][1], wv0, rr1); fma2(acc[0][2], wv0, rr2); fma2(acc[0][3], wv0, rr3);
        fma2(acc[1][0], wv1, rr0); fma2(acc[1][1], wv1, rr1); fma2(acc[1][2], wv1, rr2); fma2(acc[1][3], wv1, rr3);
        fma2(acc[2][0], wv2, rr0); fma2(acc[2][1], wv2, rr1); fma2(acc[2][2], wv2, rr2); fma2(acc[2][3], wv2, rr3);
        fma2(acc[3][0], wv3, rr0); fma2(acc[3][1], wv3, rr1); fma2(acc[3][2], wv3, rr2); fma2(acc[3][3], wv3, rr3);
    }

    // ---- mask weights per w (9 taps -> 4 grouped weights / den) ----
    int rs0 = 1 - (h & 1);  // row-group of the di=0 tap
    float W00a[4], W01a[4], W10a[4], W11a[4];
    int c0a[4], c1a[4];
#pragma unroll
    for (int j = 0; j < 4; j++) {
        int w = w0 + j;
        float ur[9];
        float sum9 = 0.f;
#pragma unroll
        for (int di = 0; di < 3; di++)
#pragma unroll
            for (int dj = 0; dj < 3; dj++) {
                float v = s_res[di * 132 + w + dj];
                ur[di * 3 + dj] = v;
                sum9 += v;
            }
        float ua = sum9 * (1.f / 9.f);
        bool ui = (ur[4] - ua) > 0.f;
        float W[2][2] = {{0.f, 0.f}, {0.f, 0.f}};
        float den = 1e-6f;
        int cs0 = 1 - (w & 1);
#pragma unroll
        for (int di = 0; di < 3; di++) {
            int hh = h + di - 1;
            bool rvalid = (hh >= 0) && (hh < 128);
            int rsel = (di == 0) ? 0 : ((di == 2) ? 1 : rs0);
#pragma unroll
            for (int dj = 0; dj < 3; dj++) {
                int ww = w + dj - 1;
                bool cvalid = (ww >= 0) && (ww < 128);
                bool up = (ur[di * 3 + dj] - ua) > 0.f;
                float mk = (up == ui) ? 1.f : 0.f;
                den += mk;
                int csel = (dj == 0) ? 0 : ((dj == 2) ? 1 : cs0);
                if (rvalid && cvalid) W[rsel][csel] += mk;
            }
        }
        float rd = 1.0f / den;
        W00a[j] = W[0][0] * rd; W01a[j] = W[0][1] * rd;
        W10a[j] = W[1][0] * rd; W11a[j] = W[1][1] * rd;
        int c0 = (w - 1) >> 1; if (c0 < 0) c0 = 0;
        int c1 = (w + 1) >> 1; if (c1 > 63) c1 = 63;
        c0a[j] = c0; c1a[j] = c1;
    }

    // ---- epilogue: num/den + relu(bn2(conv2)), float4 coalesced stores ----
    float* outrow = out + (size_t)b * 64 * 16384 + (size_t)h * 128;
#pragma unroll
    for (int oo = 0; oo < 8; oo++) {
        int o = o0 + oo;
        float A = s_A[o], Bv = s_B[o];
        const float* y0p = &s_y[o * 64];
        const float* y1p = &s_y[4096 + o * 64];
        float r4[4];
#pragma unroll
        for (int j = 0; j < 4; j++) {
            float lo, hi;
            unpack2(acc[oo >> 1][j], lo, hi);
            float cv = (oo & 1) ? hi : lo;
            float conv = fmaxf(cv * A + Bv, 0.f);
            float num = W00a[j] * y0p[c0a[j]] + W01a[j] * y0p[c1a[j]]
                      + W10a[j] * y1p[c0a[j]] + W11a[j] * y1p[c1a[j]];
            r4[j] = num + conv;
        }
        *(float4*)&outrow[(size_t)o * 16384 + w0] = make_float4(r4[0], r4[1], r4[2], r4[3]);
    }
}

// ---------------------------------------------------------------------------
extern "C" void kernel_launch(void* const* d_in, const int* in_sizes, int n_in,
                              void* d_out, int out_size) {
    (void)in_sizes; (void)n_in; (void)out_size;
    const float* x   = (const float*)d_in[0];
    const float* ref = (const float*)d_in[1];
    const float* w1  = (const float*)d_in[2];
    const float* b1  = (const float*)d_in[3];
    const float* g1  = (const float*)d_in[4];
    const float* bt1 = (const float*)d_in[5];
    const float* m1  = (const float*)d_in[6];
    const float* v1  = (const float*)d_in[7];
    const float* w2  = (const float*)d_in[8];
    const float* b2  = (const float*)d_in[9];
    const float* g2  = (const float*)d_in[10];
    const float* bt2 = (const float*)d_in[11];
    const float* m2  = (const float*)d_in[12];
    const float* v2  = (const float*)d_in[13];
    float* out = (float*)d_out;

    cudaFuncSetAttribute(fuse_kernel, cudaFuncAttributeMaxDynamicSharedMemorySize,
                         FUSE_SMEM_BYTES);

    res_kernel<<<512, 256>>>(ref);
    conv1_kernel<<<dim3(64, 8), 256>>>(x, w1, b1, g1, bt1, m1, v1);
    fuse_kernel<<<dim3(128, 8), 256, FUSE_SMEM_BYTES>>>(ref, w2, b2, g2, bt2, m2, v2, out);
}

// round 4
// speedup vs baseline: 1.2997x; 1.2997x over previous
#include <cuda_runtime.h>

#define BN_EPS 1e-5f

// Scratch (allocation-free rule: __device__ globals)
__device__ __align__(16) float g_y[8 * 64 * 64 * 64];    // (b, o, hy, wy)
__device__ __align__(16) float g_res[8 * 128 * 128];     // (b, h, w)
__device__ __align__(16) float g_wt1[64 * 64];           // w1 transposed [c][o]
__device__ __align__(16) float g_wt2[64 * 64];           // w2 transposed [c][o]

// ---------------- f32x2 packed-FMA helpers (Blackwell dual-rate fp32) -------
typedef unsigned long long u64;

__device__ __forceinline__ u64 pack2(float lo, float hi) {
    u64 r;
    asm("mov.b64 %0, {%1, %2};" : "=l"(r) : "f"(lo), "f"(hi));
    return r;
}
__device__ __forceinline__ void unpack2(u64 v, float& lo, float& hi) {
    asm("mov.b64 {%0, %1}, %2;" : "=f"(lo), "=f"(hi) : "l"(v));
}
__device__ __forceinline__ void fma2(u64& d, u64 a, u64 b) {
    asm("fma.rn.f32x2 %0, %1, %2, %0;" : "+l"(d) : "l"(a), "l"(b));
}

// ---- Kernel 1: res = channel-mean of ref  +  weight transposes -------------
// Blocks [0,256): res. Each pair of threads splits 64 channels over a float4
// of pixels (32 channels each), combined via shfl — high MLP, float4 loads.
// Blocks [256,264): transpose w1, w2 into g_wt1/g_wt2 (coalesced reads).
__global__ void __launch_bounds__(256) res_prep_kernel(
    const float4* __restrict__ ref4,
    const float* __restrict__ w1, const float* __restrict__ w2)
{
    int bid = blockIdx.x, t = threadIdx.x;
    if (bid < 256) {
        int idx = bid * 256 + t;       // 65536 threads, 2 per float4-pixel
        int pix = idx >> 1, half = idx & 1;
        int b = pix >> 12, p = pix & 4095;
        const float4* src = ref4 + (size_t)b * 262144 + (size_t)half * 32 * 4096 + p;
        float sx = 0.f, sy = 0.f, sz = 0.f, sw = 0.f;
#pragma unroll
        for (int c = 0; c < 32; c++) {
            float4 v = src[(size_t)c * 4096];
            sx += v.x; sy += v.y; sz += v.z; sw += v.w;
        }
        sx += __shfl_xor_sync(0xFFFFFFFFu, sx, 1);
        sy += __shfl_xor_sync(0xFFFFFFFFu, sy, 1);
        sz += __shfl_xor_sync(0xFFFFFFFFu, sz, 1);
        sw += __shfl_xor_sync(0xFFFFFFFFu, sw, 1);
        if (half == 0) {
            const float f = 1.0f / 64.0f;
            ((float4*)g_res)[pix] = make_float4(sx * f, sy * f, sz * f, sw * f);
        }
    } else {
        int e0 = (bid - 256) * 1024 + t;
#pragma unroll
        for (int k = 0; k < 4; k++) {
            int e = e0 + k * 256;
            if (e < 4096) {
                int o = e >> 6, c = e & 63;
                g_wt1[c * 64 + o] = w1[e];
            } else {
                int e2 = e - 4096;
                int o = e2 >> 6, c = e2 & 63;
                g_wt2[c * 64 + o] = w2[e2];
            }
        }
    }
}

// ---------------- Kernel 2: y = relu(bn1(conv1(x))) at 64x64 ----------------
__global__ void __launch_bounds__(256) conv1_kernel(
    const float* __restrict__ x,
    const float* __restrict__ b1, const float* __restrict__ g1,
    const float* __restrict__ bt1, const float* __restrict__ m1,
    const float* __restrict__ v1)
{
    __shared__ __align__(16) float s_x[64 * 64];    // [c][w]
    __shared__ __align__(16) float s_wt[64 * 64];   // [c][o] transposed
    __shared__ float s_A[64], s_B[64];

    int h = blockIdx.x, b = blockIdx.y;
    int t = threadIdx.x;

    if (t < 64) {
        float sc = g1[t] * rsqrtf(v1[t] + BN_EPS);
        s_A[t] = sc;
        s_B[t] = b1[t] * sc + bt1[t] - m1[t] * sc;
    }
    const float* xrow = x + (size_t)b * 64 * 4096 + (size_t)h * 64;
    for (int i = t; i < 1024; i += 256) {           // float4 loads: 64c x 16 quads
        int c = i >> 4, w4 = (i & 15) * 4;
        *(float4*)&s_x[c * 64 + w4] = *(const float4*)&xrow[(size_t)c * 4096 + w4];
    }
    for (int i = t; i < 1024; i += 256)             // coalesced transposed weights
        ((float4*)s_wt)[i] = ((const float4*)g_wt1)[i];
    __syncthreads();

    int wg = t & 31, og = t >> 5;
    int w0 = wg * 2, o0 = og * 8;

    u64 acc[4][2];                                  // [o-pair][w]
#pragma unroll
    for (int i = 0; i < 4; i++)
#pragma unroll
        for (int j = 0; j < 2; j++) acc[i][j] = 0ull;

#pragma unroll 8
    for (int c = 0; c < 64; c++) {
        float2 rv = *(const float2*)&s_x[c * 64 + w0];
        u64 r0 = pack2(rv.x, rv.x);
        u64 r1 = pack2(rv.y, rv.y);
        const u64* wp = (const u64*)&s_wt[c * 64 + o0];
        u64 wv0 = wp[0], wv1 = wp[1], wv2 = wp[2], wv3 = wp[3];
        fma2(acc[0][0], wv0, r0); fma2(acc[0][1], wv0, r1);
        fma2(acc[1][0], wv1, r0); fma2(acc[1][1], wv1, r1);
        fma2(acc[2][0], wv2, r0); fma2(acc[2][1], wv2, r1);
        fma2(acc[3][0], wv3, r0); fma2(acc[3][1], wv3, r1);
    }

    float* ybase = g_y + (size_t)b * 64 * 4096 + (size_t)h * 64;
#pragma unroll
    for (int i = 0; i < 4; i++) {
        int oA = o0 + 2 * i, oB = oA + 1;
        float A0 = s_A[oA], B0 = s_B[oA];
        float A1 = s_A[oB], B1 = s_B[oB];
#pragma unroll
        for (int j = 0; j < 2; j++) {
            float lo, hi;
            unpack2(acc[i][j], lo, hi);
            ybase[(size_t)oA * 4096 + w0 + j] = fmaxf(lo * A0 + B0, 0.f);
            ybase[(size_t)oB * 4096 + w0 + j] = fmaxf(hi * A1 + B1, 0.f);
        }
    }
}

// ---------------- Kernel 3: fused mask + aggregate + conv2 ------------------
#define FUSE_SMEM_FLOATS (8192 + 4096 + 8192 + 396 + 64 + 64)
#define FUSE_SMEM_BYTES  (FUSE_SMEM_FLOATS * 4)

__global__ void __launch_bounds__(256, 2) fuse_kernel(
    const float* __restrict__ ref,
    const float* __restrict__ b2,  const float* __restrict__ g2,
    const float* __restrict__ bt2, const float* __restrict__ m2,
    const float* __restrict__ v2,  float* __restrict__ out)
{
    extern __shared__ float sm[];
    float* s_ref = sm;              // 8192
    float* s_wt  = sm + 8192;       // 4096
    float* s_y   = sm + 12288;      // 8192 (buf0 then buf1)
    float* s_res = sm + 20480;      // 396
    float* s_A   = sm + 20876;      // 64
    float* s_B   = sm + 20940;      // 64

    int h = blockIdx.x, b = blockIdx.y;
    int t = threadIdx.x;

    if (t < 64) {
        float sc = g2[t] * rsqrtf(v2[t] + BN_EPS);
        s_A[t] = sc;
        s_B[t] = b2[t] * sc + bt2[t] - m2[t] * sc;
    }

    const float* rrow = ref + (size_t)b * 64 * 16384 + (size_t)h * 128;
    for (int i = t; i < 2048; i += 256) {           // float4: 64c x 32 quads
        int c = i >> 5, w4 = (i & 31) * 4;
        *(float4*)&s_ref[c * 128 + w4] = *(const float4*)&rrow[(size_t)c * 16384 + w4];
    }
    for (int i = t; i < 1024; i += 256)             // coalesced transposed weights
        ((float4*)s_wt)[i] = ((const float4*)g_wt2)[i];

    // y rows: the 9 upsampled taps collapse to 2 y rows
    int r0 = (h - 1) >> 1; if (r0 < 0) r0 = 0;
    int r1 = (h + 1) >> 1; if (r1 > 63) r1 = 63;
    const float* ybase = g_y + (size_t)b * 64 * 4096;
    for (int i = t; i < 1024; i += 256) {           // float4: 64o x 16 quads
        int o = i >> 4, w4 = (i & 15) * 4;
        *(float4*)&s_y[o * 64 + w4]        = *(const float4*)&ybase[(size_t)o * 4096 + r0 * 64 + w4];
        *(float4*)&s_y[4096 + o * 64 + w4] = *(const float4*)&ybase[(size_t)o * 4096 + r1 * 64 + w4];
    }

    // res rows, zero padded: s_res[j*132 + (w+1)] = res[h-1+j][w]
    for (int i = t; i < 3 * 132; i += 256) {
        int j = i / 132, col = i % 132;
        int rr = h - 1 + j, wc = col - 1;
        float v = 0.f;
        if (col < 130 && rr >= 0 && rr < 128 && wc >= 0 && wc < 128)
            v = g_res[((size_t)b * 128 + rr) * 128 + wc];
        s_res[i] = v;
    }
    __syncthreads();

    int wg = t & 31, og = t >> 5;
    int w0 = wg * 4, o0 = og * 8;

    // ---- conv2 GEMM: 8 o x 4 w per thread, f32x2 packed along o ----
    u64 acc[4][4];
#pragma unroll
    for (int i = 0; i < 4; i++)
#pragma unroll
        for (int j = 0; j < 4; j++) acc[i][j] = 0ull;

#pragma unroll 8
    for (int c = 0; c < 64; c++) {
        float4 rv = *(const float4*)&s_ref[c * 128 + w0];
        u64 rr0 = pack2(rv.x, rv.x);
        u64 rr1 = pack2(rv.y, rv.y);
        u64 rr2 = pack2(rv.z, rv.z);
        u64 rr3 = pack2(rv.w, rv.w);
        const u64* wp = (const u64*)&s_wt[c * 64 + o0];
        u64 wv0 = wp[0], wv1 = wp[1], wv2 = wp[2], wv3 = wp[3];
        fma2(acc[0][0], wv0, rr0); fma2(acc[0][1], wv0, rr1); fma2(acc[0][2], wv0, rr2); fma2(acc[0][3], wv0, rr3);
        fma2(acc[1][0], wv1, rr0); fma2(acc[1][1], wv1, rr1); fma2(acc[1][2], wv1, rr2); fma2(acc[1][3], wv1, rr3);
        fma2(acc[2][0], wv2, rr0); fma2(acc[2][1], wv2, rr1); fma2(acc[2][2], wv2, rr2); fma2(acc[2][3], wv2, rr3);
        fma2(acc[3][0], wv3, rr0); fma2(acc[3][1], wv3, rr1); fma2(acc[3][2], wv3, rr2); fma2(acc[3][3], wv3, rr3);
    }

    // ---- mask weights per w (9 taps -> 4 grouped weights / den) ----
    int rs0 = 1 - (h & 1);  // row-group of the di=0 tap
    float W00a[4], W01a[4], W10a[4], W11a[4];
    int c0a[4], c1a[4];
#pragma unroll
    for (int j = 0; j < 4; j++) {
        int w = w0 + j;
        float ur[9];
        float sum9 = 0.f;
#pragma unroll
        for (int di = 0; di < 3; di++)
#pragma unroll
            for (int dj = 0; dj < 3; dj++) {
                float v = s_res[di * 132 + w + dj];
                ur[di * 3 + dj] = v;
                sum9 += v;
            }
        float ua = sum9 * (1.f / 9.f);
        bool ui = (ur[4] - ua) > 0.f;
        float W[2][2] = {{0.f, 0.f}, {0.f, 0.f}};
        float den = 1e-6f;
        int cs0 = 1 - (w & 1);
#pragma unroll
        for (int di = 0; di < 3; di++) {
            int hh = h + di - 1;
            bool rvalid = (hh >= 0) && (hh < 128);
            int rsel = (di == 0) ? 0 : ((di == 2) ? 1 : rs0);
#pragma unroll
            for (int dj = 0; dj < 3; dj++) {
                int ww = w + dj - 1;
                bool cvalid = (ww >= 0) && (ww < 128);
                bool up = (ur[di * 3 + dj] - ua) > 0.f;
                float mk = (up == ui) ? 1.f : 0.f;
                den += mk;
                int csel = (dj == 0) ? 0 : ((dj == 2) ? 1 : cs0);
                if (rvalid && cvalid) W[rsel][csel] += mk;
            }
        }
        float rd = 1.0f / den;
        W00a[j] = W[0][0] * rd; W01a[j] = W[0][1] * rd;
        W10a[j] = W[1][0] * rd; W11a[j] = W[1][1] * rd;
        int c0 = (w - 1) >> 1; if (c0 < 0) c0 = 0;
        int c1 = (w + 1) >> 1; if (c1 > 63) c1 = 63;
        c0a[j] = c0; c1a[j] = c1;
    }

    // ---- epilogue: num/den + relu(bn2(conv2)), float4 coalesced stores ----
    float* outrow = out + (size_t)b * 64 * 16384 + (size_t)h * 128;
#pragma unroll
    for (int oo = 0; oo < 8; oo++) {
        int o = o0 + oo;
        float A = s_A[o], Bv = s_B[o];
        const float* y0p = &s_y[o * 64];
        const float* y1p = &s_y[4096 + o * 64];
        float r4[4];
#pragma unroll
        for (int j = 0; j < 4; j++) {
            float lo, hi;
            unpack2(acc[oo >> 1][j], lo, hi);
            float cv = (oo & 1) ? hi : lo;
            float conv = fmaxf(cv * A + Bv, 0.f);
            float num = W00a[j] * y0p[c0a[j]] + W01a[j] * y0p[c1a[j]]
                      + W10a[j] * y1p[c0a[j]] + W11a[j] * y1p[c1a[j]];
            r4[j] = num + conv;
        }
        *(float4*)&outrow[(size_t)o * 16384 + w0] = make_float4(r4[0], r4[1], r4[2], r4[3]);
    }
}

// ---------------------------------------------------------------------------
extern "C" void kernel_launch(void* const* d_in, const int* in_sizes, int n_in,
                              void* d_out, int out_size) {
    (void)in_sizes; (void)n_in; (void)out_size;
    const float* x   = (const float*)d_in[0];
    const float* ref = (const float*)d_in[1];
    const float* w1  = (const float*)d_in[2];
    const float* b1  = (const float*)d_in[3];
    const float* g1  = (const float*)d_in[4];
    const float* bt1 = (const float*)d_in[5];
    const float* m1  = (const float*)d_in[6];
    const float* v1  = (const float*)d_in[7];
    const float* w2  = (const float*)d_in[8];
    const float* b2  = (const float*)d_in[9];
    const float* g2  = (const float*)d_in[10];
    const float* bt2 = (const float*)d_in[11];
    const float* m2  = (const float*)d_in[12];
    const float* v2  = (const float*)d_in[13];
    float* out = (float*)d_out;

    cudaFuncSetAttribute(fuse_kernel, cudaFuncAttributeMaxDynamicSharedMemorySize,
                         FUSE_SMEM_BYTES);

    res_prep_kernel<<<264, 256>>>((const float4*)ref, w1, w2);
    conv1_kernel<<<dim3(64, 8), 256>>>(x, b1, g1, bt1, m1, v1);
    fuse_kernel<<<dim3(128, 8), 256, FUSE_SMEM_BYTES>>>(ref, b2, g2, bt2, m2, v2, out);
}

// round 5
// speedup vs baseline: 1.4799x; 1.1386x over previous
#include <cuda_runtime.h>

#define BN_EPS 1e-5f

// Scratch (allocation-free rule: __device__ globals)
__device__ __align__(16) float g_y[8 * 64 * 64 * 64];    // (b, o, hy, wy)
__device__ __align__(16) float g_res[8 * 128 * 128];     // (b, h, w)
__device__ __align__(16) float g_wt1[64 * 64];           // w1 transposed [c][o]
__device__ __align__(16) float g_wt2[64 * 64];           // w2 transposed [c][o]

// ---------------- f32x2 packed-FMA helpers (Blackwell dual-rate fp32) -------
typedef unsigned long long u64;

__device__ __forceinline__ u64 pack2(float lo, float hi) {
    u64 r;
    asm("mov.b64 %0, {%1, %2};" : "=l"(r) : "f"(lo), "f"(hi));
    return r;
}
__device__ __forceinline__ void unpack2(u64 v, float& lo, float& hi) {
    asm("mov.b64 {%0, %1}, %2;" : "=f"(lo), "=f"(hi) : "l"(v));
}
__device__ __forceinline__ void fma2(u64& d, u64 a, u64 b) {
    asm("fma.rn.f32x2 %0, %1, %2, %0;" : "+l"(d) : "l"(a), "l"(b));
}

__device__ __forceinline__ void cp_async16(void* smem_dst, const void* gptr) {
    unsigned sa = (unsigned)__cvta_generic_to_shared(smem_dst);
    asm volatile("cp.async.cg.shared.global [%0], [%1], 16;" :: "r"(sa), "l"(gptr));
}
__device__ __forceinline__ void cp_commit() {
    asm volatile("cp.async.commit_group;");
}
template <int N>
__device__ __forceinline__ void cp_wait() {
    asm volatile("cp.async.wait_group %0;" :: "n"(N));
}

// ---- Kernel 1: res = channel-mean of ref  +  weight transposes -------------
// Blocks [0,512): res. 4 threads per float4-pixel, 16 channels each, combined
// via shfl_xor(1),shfl_xor(2). Blocks [512,520): transpose w1/w2.
__global__ void __launch_bounds__(256) res_prep_kernel(
    const float4* __restrict__ ref4,
    const float* __restrict__ w1, const float* __restrict__ w2)
{
    int bid = blockIdx.x, t = threadIdx.x;
    if (bid < 512) {
        int idx = bid * 256 + t;          // 131072 threads, 4 per float4-pixel
        int quad = idx >> 2, q = idx & 3;
        int b = quad >> 12, p = quad & 4095;
        const float4* src = ref4 + (size_t)b * 262144 + (size_t)q * 16 * 4096 + p;
        float sx = 0.f, sy = 0.f, sz = 0.f, sw = 0.f;
#pragma unroll
        for (int c = 0; c < 16; c++) {
            float4 v = src[(size_t)c * 4096];
            sx += v.x; sy += v.y; sz += v.z; sw += v.w;
        }
#pragma unroll
        for (int m = 1; m <= 2; m <<= 1) {
            sx += __shfl_xor_sync(0xFFFFFFFFu, sx, m);
            sy += __shfl_xor_sync(0xFFFFFFFFu, sy, m);
            sz += __shfl_xor_sync(0xFFFFFFFFu, sz, m);
            sw += __shfl_xor_sync(0xFFFFFFFFu, sw, m);
        }
        if (q == 0) {
            const float f = 1.0f / 64.0f;
            ((float4*)g_res)[quad] = make_float4(sx * f, sy * f, sz * f, sw * f);
        }
    } else {
        int e0 = (bid - 512) * 1024 + t;
#pragma unroll
        for (int k = 0; k < 4; k++) {
            int e = e0 + k * 256;
            if (e < 4096) {
                int o = e >> 6, c = e & 63;
                g_wt1[c * 64 + o] = w1[e];
            } else {
                int e2 = e - 4096;
                int o = e2 >> 6, c = e2 & 63;
                g_wt2[c * 64 + o] = w2[e2];
            }
        }
    }
}

// ---------------- Kernel 2: y = relu(bn1(conv1(x))) at 64x64 ----------------
__global__ void __launch_bounds__(256) conv1_kernel(
    const float* __restrict__ x,
    const float* __restrict__ b1, const float* __restrict__ g1,
    const float* __restrict__ bt1, const float* __restrict__ m1,
    const float* __restrict__ v1)
{
    __shared__ __align__(16) float s_x[64 * 64];    // [c][w]
    __shared__ __align__(16) float s_wt[64 * 64];   // [c][o] transposed
    __shared__ float s_A[64], s_B[64];

    int h = blockIdx.x, b = blockIdx.y;
    int t = threadIdx.x;

    if (t < 64) {
        float sc = g1[t] * rsqrtf(v1[t] + BN_EPS);
        s_A[t] = sc;
        s_B[t] = b1[t] * sc + bt1[t] - m1[t] * sc;
    }
    const float* xrow = x + (size_t)b * 64 * 4096 + (size_t)h * 64;
    for (int i = t; i < 1024; i += 256) {           // float4 loads: 64c x 16 quads
        int c = i >> 4, w4 = (i & 15) * 4;
        *(float4*)&s_x[c * 64 + w4] = *(const float4*)&xrow[(size_t)c * 4096 + w4];
    }
    for (int i = t; i < 1024; i += 256)             // coalesced transposed weights
        ((float4*)s_wt)[i] = ((const float4*)g_wt1)[i];
    __syncthreads();

    int wg = t & 31, og = t >> 5;
    int w0 = wg * 2, o0 = og * 8;

    u64 acc[4][2];                                  // [o-pair][w]
#pragma unroll
    for (int i = 0; i < 4; i++)
#pragma unroll
        for (int j = 0; j < 2; j++) acc[i][j] = 0ull;

#pragma unroll 8
    for (int c = 0; c < 64; c++) {
        float2 rv = *(const float2*)&s_x[c * 64 + w0];
        u64 r0 = pack2(rv.x, rv.x);
        u64 r1 = pack2(rv.y, rv.y);
        const u64* wp = (const u64*)&s_wt[c * 64 + o0];
        u64 wv0 = wp[0], wv1 = wp[1], wv2 = wp[2], wv3 = wp[3];
        fma2(acc[0][0], wv0, r0); fma2(acc[0][1], wv0, r1);
        fma2(acc[1][0], wv1, r0); fma2(acc[1][1], wv1, r1);
        fma2(acc[2][0], wv2, r0); fma2(acc[2][1], wv2, r1);
        fma2(acc[3][0], wv3, r0); fma2(acc[3][1], wv3, r1);
    }

    float* ybase = g_y + (size_t)b * 64 * 4096 + (size_t)h * 64;
#pragma unroll
    for (int i = 0; i < 4; i++) {
        int oA = o0 + 2 * i, oB = oA + 1;
        float A0 = s_A[oA], B0 = s_B[oA];
        float A1 = s_A[oB], B1 = s_B[oB];
#pragma unroll
        for (int j = 0; j < 2; j++) {
            float lo, hi;
            unpack2(acc[i][j], lo, hi);
            ybase[(size_t)oA * 4096 + w0 + j] = fmaxf(lo * A0 + B0, 0.f);
            ybase[(size_t)oB * 4096 + w0 + j] = fmaxf(hi * A1 + B1, 0.f);
        }
    }
}

// ---------------- Kernel 3: fused mask + aggregate + conv2 ------------------
// cp.async double-buffered ref chunks (16 channels each), 3 blocks/SM.
// smem (floats): buf0 2048 | buf1 2048 | wt 4096 | y 8192 | res 396 | A,B 128
#define FUSE_SMEM_FLOATS (2048 + 2048 + 4096 + 8192 + 396 + 64 + 64)
#define FUSE_SMEM_BYTES  (FUSE_SMEM_FLOATS * 4)

__global__ void __launch_bounds__(256, 3) fuse_kernel(
    const float* __restrict__ ref,
    const float* __restrict__ b2,  const float* __restrict__ g2,
    const float* __restrict__ bt2, const float* __restrict__ m2,
    const float* __restrict__ v2,  float* __restrict__ out)
{
    extern __shared__ float sm[];
    float* s_buf[2] = { sm, sm + 2048 };
    float* s_wt  = sm + 4096;       // 4096
    float* s_y   = sm + 8192;       // 8192 (buf0 then buf1)
    float* s_res = sm + 16384;      // 396
    float* s_A   = sm + 16780;      // 64
    float* s_B   = sm + 16844;      // 64

    int h = blockIdx.x, b = blockIdx.y;
    int t = threadIdx.x;

    const float* rrow = ref + (size_t)b * 64 * 16384 + (size_t)h * 128;

    // issue chunk k (16 channels of the ref row) into buffer `buf`
    auto issue = [&](int k, float* buf) {
#pragma unroll
        for (int r = 0; r < 2; r++) {
            int i = t + r * 256;                      // 512 float4s per chunk
            int cl = i >> 5, w4 = (i & 31) << 2;
            cp_async16(buf + cl * 128 + w4,
                       rrow + (size_t)(k * 16 + cl) * 16384 + w4);
        }
        cp_commit();
    };
    issue(0, s_buf[0]);
    issue(1, s_buf[1]);

    // regular prologue loads overlap with the in-flight cp.async traffic
    if (t < 64) {
        float sc = g2[t] * rsqrtf(v2[t] + BN_EPS);
        s_A[t] = sc;
        s_B[t] = b2[t] * sc + bt2[t] - m2[t] * sc;
    }
    for (int i = t; i < 1024; i += 256)               // transposed w2 (coalesced)
        ((float4*)s_wt)[i] = ((const float4*)g_wt2)[i];

    // y rows: the 9 upsampled taps collapse to 2 y rows
    int r0 = (h - 1) >> 1; if (r0 < 0) r0 = 0;
    int r1 = (h + 1) >> 1; if (r1 > 63) r1 = 63;
    const float* ybase = g_y + (size_t)b * 64 * 4096;
    for (int i = t; i < 1024; i += 256) {             // float4: 64o x 16 quads
        int o = i >> 4, w4 = (i & 15) * 4;
        *(float4*)&s_y[o * 64 + w4]        = *(const float4*)&ybase[(size_t)o * 4096 + r0 * 64 + w4];
        *(float4*)&s_y[4096 + o * 64 + w4] = *(const float4*)&ybase[(size_t)o * 4096 + r1 * 64 + w4];
    }

    // res rows, zero padded: s_res[j*132 + (w+1)] = res[h-1+j][w]
    for (int i = t; i < 3 * 132; i += 256) {
        int j = i / 132, col = i % 132;
        int rr = h - 1 + j, wc = col - 1;
        float v = 0.f;
        if (col < 130 && rr >= 0 && rr < 128 && wc >= 0 && wc < 128)
            v = g_res[((size_t)b * 128 + rr) * 128 + wc];
        s_res[i] = v;
    }

    int wg = t & 31, og = t >> 5;
    int w0 = wg * 4, o0 = og * 8;

    // ---- conv2 GEMM: 8 o x 4 w per thread, f32x2 packed along o,
    //      double-buffered over 4 chunks of 16 channels ----
    u64 acc[4][4];
#pragma unroll
    for (int i = 0; i < 4; i++)
#pragma unroll
        for (int j = 0; j < 4; j++) acc[i][j] = 0ull;

#pragma unroll
    for (int k = 0; k < 4; k++) {
        if (k < 3) cp_wait<1>(); else cp_wait<0>();
        __syncthreads();                              // chunk k visible to all
        const float* bufp = s_buf[k & 1];
#pragma unroll
        for (int cl = 0; cl < 16; cl++) {
            int c = k * 16 + cl;
            float4 rv = *(const float4*)&bufp[cl * 128 + w0];
            u64 rr0 = pack2(rv.x, rv.x);
            u64 rr1 = pack2(rv.y, rv.y);
            u64 rr2 = pack2(rv.z, rv.z);
            u64 rr3 = pack2(rv.w, rv.w);
            const u64* wp = (const u64*)&s_wt[c * 64 + o0];
            u64 wv0 = wp[0], wv1 = wp[1], wv2 = wp[2], wv3 = wp[3];
            fma2(acc[0][0], wv0, rr0); fma2(acc[0][1], wv0, rr1); fma2(acc[0][2], wv0, rr2); fma2(acc[0][3], wv0, rr3);
            fma2(acc[1][0], wv1, rr0); fma2(acc[1][1], wv1, rr1); fma2(acc[1][2], wv1, rr2); fma2(acc[1][3], wv1, rr3);
            fma2(acc[2][0], wv2, rr0); fma2(acc[2][1], wv2, rr1); fma2(acc[2][2], wv2, rr2); fma2(acc[2][3], wv2, rr3);
            fma2(acc[3][0], wv3, rr0); fma2(acc[3][1], wv3, rr1); fma2(acc[3][2], wv3, rr2); fma2(acc[3][3], wv3, rr3);
        }
        if (k + 2 < 4) {
            __syncthreads();                          // everyone done with buf[k&1]
            issue(k + 2, s_buf[k & 1]);
        }
    }

    // ---- mask weights per w (9 taps -> 4 grouped weights / den) ----
    int rs0 = 1 - (h & 1);  // row-group of the di=0 tap
    float W00a[4], W01a[4], W10a[4], W11a[4];
    int c0a[4], c1a[4];
#pragma unroll
    for (int j = 0; j < 4; j++) {
        int w = w0 + j;
        float ur[9];
        float sum9 = 0.f;
#pragma unroll
        for (int di = 0; di < 3; di++)
#pragma unroll
            for (int dj = 0; dj < 3; dj++) {
                float v = s_res[di * 132 + w + dj];
                ur[di * 3 + dj] = v;
                sum9 += v;
            }
        float ua = sum9 * (1.f / 9.f);
        bool ui = (ur[4] - ua) > 0.f;
        float W[2][2] = {{0.f, 0.f}, {0.f, 0.f}};
        float den = 1e-6f;
        int cs0 = 1 - (w & 1);
#pragma unroll
        for (int di = 0; di < 3; di++) {
            int hh = h + di - 1;
            bool rvalid = (hh >= 0) && (hh < 128);
            int rsel = (di == 0) ? 0 : ((di == 2) ? 1 : rs0);
#pragma unroll
            for (int dj = 0; dj < 3; dj++) {
                int ww = w + dj - 1;
                bool cvalid = (ww >= 0) && (ww < 128);
                bool up = (ur[di * 3 + dj] - ua) > 0.f;
                float mk = (up == ui) ? 1.f : 0.f;
                den += mk;
                int csel = (dj == 0) ? 0 : ((dj == 2) ? 1 : cs0);
                if (rvalid && cvalid) W[rsel][csel] += mk;
            }
        }
        float rd = 1.0f / den;
        W00a[j] = W[0][0] * rd; W01a[j] = W[0][1] * rd;
        W10a[j] = W[1][0] * rd; W11a[j] = W[1][1] * rd;
        int c0 = (w - 1) >> 1; if (c0 < 0) c0 = 0;
        int c1 = (w + 1) >> 1; if (c1 > 63) c1 = 63;
        c0a[j] = c0; c1a[j] = c1;
    }

    // ---- epilogue: num/den + relu(bn2(conv2)), float4 coalesced stores ----
    float* outrow = out + (size_t)b * 64 * 16384 + (size_t)h * 128;
#pragma unroll
    for (int oo = 0; oo < 8; oo++) {
        int o = o0 + oo;
        float A = s_A[o], Bv = s_B[o];
        const float* y0p = &s_y[o * 64];
        const float* y1p = &s_y[4096 + o * 64];
        float r4[4];
#pragma unroll
        for (int j = 0; j < 4; j++) {
            float lo, hi;
            unpack2(acc[oo >> 1][j], lo, hi);
            float cv = (oo & 1) ? hi : lo;
            float conv = fmaxf(cv * A + Bv, 0.f);
            float num = W00a[j] * y0p[c0a[j]] + W01a[j] * y0p[c1a[j]]
                      + W10a[j] * y1p[c0a[j]] + W11a[j] * y1p[c1a[j]];
            r4[j] = num + conv;
        }
        *(float4*)&outrow[(size_t)o * 16384 + w0] = make_float4(r4[0], r4[1], r4[2], r4[3]);
    }
}

// ---------------------------------------------------------------------------
extern "C" void kernel_launch(void* const* d_in, const int* in_sizes, int n_in,
                              void* d_out, int out_size) {
    (void)in_sizes; (void)n_in; (void)out_size;
    const float* x   = (const float*)d_in[0];
    const float* ref = (const float*)d_in[1];
    const float* w1  = (const float*)d_in[2];
    const float* b1  = (const float*)d_in[3];
    const float* g1  = (const float*)d_in[4];
    const float* bt1 = (const float*)d_in[5];
    const float* m1  = (const float*)d_in[6];
    const float* v1  = (const float*)d_in[7];
    const float* w2  = (const float*)d_in[8];
    const float* b2  = (const float*)d_in[9];
    const float* g2  = (const float*)d_in[10];
    const float* bt2 = (const float*)d_in[11];
    const float* m2  = (const float*)d_in[12];
    const float* v2  = (const float*)d_in[13];
    float* out = (float*)d_out;

    cudaFuncSetAttribute(fuse_kernel, cudaFuncAttributeMaxDynamicSharedMemorySize,
                         FUSE_SMEM_BYTES);

    res_prep_kernel<<<520, 256>>>((const float4*)ref, w1, w2);
    conv1_kernel<<<dim3(64, 8), 256>>>(x, b1, g1, bt1, m1, v1);
    fuse_kernel<<<dim3(128, 8), 256, FUSE_SMEM_BYTES>>>(ref, b2, g2, bt2, m2, v2, out);
}